// round 11
// baseline (speedup 1.0000x reference)
#include <cuda_runtime.h>
#include <cstdint>

// ConditionalSplineSQ2D: out[b] = sum_{g,h,c} param[b,g,h,ii]*param[b,g,h,jj]*coef[g,h,c]
// B=4096, G*G=961 cells, P=8, C=36. Pure HBM stream: 126MB read once.
//
// Latency-equilibrium fix: 4-stage per-thread cp.async ring (124KB/SM truly
// in flight, LDGSTS has no depth cap and uses no registers), swizzled slots
// (t ^ ((t>>3)&3))*16 so both the LDGSTS smem writes and the consumer
// LDS.128s are bank-conflict-free (R2/R3's hidden killer was 8-way conflicts
// at slot=t*32). Each thread reads only its own slot -> per-thread
// commit_group/wait_group, NO barriers/mbarriers in the loop. Thread t owns
// cell t with 36 coefs in registers. Per-warp staggered b-start keeps DRAM
// demand time-uniform. Epilogue: warp-reduce + part[k][warp] STS in-loop,
// one __syncthreads after, warp w finalizes b_w.

#define GG      961
#define CC      36
#define NTHR    992
#define NWARP   31
#define DEPTH   4
#define CHUNK   (NTHR * 16)          // 15872 B per chunk region
#define STAGE   (2 * CHUNK)          // 31744 B per stage
#define SMEM_DYN (DEPTH * STAGE)     // 126976 B ring
#define MAXK    28

extern __shared__ char ring[];

__device__ __forceinline__ void cp16(uint32_t dst_smem, const void* src) {
    asm volatile("cp.async.cg.shared.global [%0], [%1], 16;"
                 :: "r"(dst_smem), "l"(src) : "memory");
}
__device__ __forceinline__ void cp_commit() {
    asm volatile("cp.async.commit_group;" ::: "memory");
}
template <int N>
__device__ __forceinline__ void cp_wait() {
    asm volatile("cp.async.wait_group %0;" :: "n"(N) : "memory");
}

__global__ __launch_bounds__(NTHR, 1)
void sq2d_kernel(const float* __restrict__ param,
                 const float* __restrict__ coef,
                 float* __restrict__ out,
                 int nB, int stride)
{
    __shared__ float part[MAXK * 32];   // [k][warp] per-warp partials

    const int tid  = threadIdx.x;
    const int lane = tid & 31;
    const int warp = tid >> 5;
    const bool active = (tid < GG);
    const int cell = active ? tid : (GG - 1);   // pad threads dup cell 960

    // 36 coefficients in registers (0 for pad threads).
    float cf[CC];
#pragma unroll
    for (int c = 0; c < CC; c++)
        cf[c] = active ? coef[cell * CC + c] : 0.0f;

    const int bid = blockIdx.x;
    const int K = (nB - bid + stride - 1) / stride;   // 26..27 b's for this CTA

    const char* gbase = (const char*)param + (size_t)cell * 32
                      + (size_t)bid * (size_t)GG * 32;
    const size_t bstep = (size_t)GG * 32 * (size_t)stride;

    // Swizzled per-thread slot: conflict-free for LDS.128 and LDGSTS writes.
    const uint32_t slot = (uint32_t)((tid ^ ((tid >> 3) & 3)) * 16);
    uint32_t rbase;
    asm("{ .reg .u64 t; cvta.to.shared.u64 t, %1; cvt.u32.u64 %0, t; }"
        : "=r"(rbase) : "l"(ring));
    rbase += slot;

    // Staggered start within this CTA's b-list.
    int k0 = (warp * K) / NWARP;
    if (k0 >= K) k0 = K - 1;

    int kc = k0;                                 // consume index (wrapped)
    int kl = k0;                                 // load index (wrapped)
    const char* lptr = gbase + (size_t)kl * bstep;

    // Prefill DEPTH stages with the thread's next DEPTH b's.
#pragma unroll
    for (int s = 0; s < DEPTH; s++) {
        if (s < K) {
            uint32_t d = rbase + s * STAGE;
            cp16(d, lptr);
            cp16(d + CHUNK, lptr + 16);
        }
        cp_commit();
        kl++; lptr += bstep;
        if (kl >= K) { kl = 0; lptr = gbase; }
    }

    int s = 0;
#pragma unroll 1
    for (int j = 0; j < K; j++) {
        cp_wait<DEPTH - 1>();    // oldest stage landed (own copies only)

        const float4* q0 = (const float4*)(ring + slot + s * STAGE);
        const float4* q1 = (const float4*)(ring + slot + s * STAGE + CHUNK);
        float4 a0 = q0[0];
        float4 a1 = q1[0];

        const int kout = kc;
        kc++;
        if (kc >= K) kc = 0;

        // Refill the just-consumed stage (skip the final DEPTH iterations so
        // no wasted DRAM traffic; commit stays uniform for group accounting).
        if (j + DEPTH < K) {
            uint32_t d = rbase + s * STAGE;
            cp16(d, lptr);
            cp16(d + CHUNK, lptr + 16);
        }
        cp_commit();
        kl++; lptr += bstep;
        if (kl >= K) { kl = 0; lptr = gbase; }

        float pv[8] = { a0.x, a0.y, a0.z, a0.w, a1.x, a1.y, a1.z, a1.w };

        // acc = sum_{i<=j} cf[c(i,j)] * p_i * p_j : 44 FMA.
        float acc = 0.0f;
        int c = 0;
#pragma unroll
        for (int i = 0; i < 8; i++) {
            float q = 0.0f;
#pragma unroll
            for (int jj = i; jj < 8; jj++)
                q = fmaf(cf[c++], pv[jj], q);
            acc = fmaf(pv[i], q, acc);
        }

        // Warp reduce; one STS per warp per b. No block coupling in the loop.
#pragma unroll
        for (int o = 16; o > 0; o >>= 1)
            acc += __shfl_xor_sync(0xffffffffu, acc, o);
        if (lane == 0)
            part[kout * 32 + warp] = acc;

        s = (s + 1) & (DEPTH - 1);
    }

    __syncthreads();   // the only block barrier

    // Warp w finalizes b = bid + w*stride.
    if (warp < K) {
        float v = (lane < NWARP) ? part[warp * 32 + lane] : 0.0f;
#pragma unroll
        for (int o = 16; o > 0; o >>= 1)
            v += __shfl_xor_sync(0xffffffffu, v, o);
        if (lane == 0)
            out[bid + warp * stride] = v;
    }
}

extern "C" void kernel_launch(void* const* d_in, const int* in_sizes, int n_in,
                              void* d_out, int out_size)
{
    const float* param = (const float*)d_in[0];   // [B, 31, 31, 8] f32
    const float* coef  = (const float*)d_in[1];   // [31, 31, 36]   f32
    float* out = (float*)d_out;                    // [B] f32

    const int nB = in_sizes[0] / (GG * 8);

    static int configured = -1;
    if (configured < 0) {
        cudaFuncSetAttribute(sq2d_kernel,
                             cudaFuncAttributeMaxDynamicSharedMemorySize, SMEM_DYN);
        configured = 1;
    }

    int dev = 0, sms = 0;
    cudaGetDevice(&dev);
    cudaDeviceGetAttribute(&sms, cudaDevAttrMultiProcessorCount, dev);
    if (sms <= 0) sms = 148;

    int grid = sms;
    const int min_grid = (nB + MAXK - 1) / MAXK;   // keep K <= MAXK
    if (grid < min_grid) grid = min_grid;
    if (grid > nB) grid = nB;

    sq2d_kernel<<<grid, NTHR, SMEM_DYN>>>(param, coef, out, nB, grid);
}

// round 12
// speedup vs baseline: 1.3069x; 1.3069x over previous
#include <cuda_runtime.h>
#include <cstdint>

// ConditionalSplineSQ2D: out[b] = sum_{g,h,c} param[b,g,h,ii]*param[b,g,h,jj]*coef[g,h,c]
// B=4096, G*G=961 cells, P=8, C=36. Pure HBM stream: 126MB read once.
//
// Triple-decker latency pipeline, all register-file-neutral:
//   prefetch.global.L2 at distance 8  -- carries DRAM latency (no regs)
//   prefetch.global.L1 at distance 2  -- carries L2 latency   (no regs)
//   register double-buffer at distance 1 (forced movs, R8) -- carries L1 hit
// R8/R9/R10 each validated one stage independently (+0.1..0.7us each);
// this stacks them. Partials epilogue is the tiny part[k][warp] variant
// (3.5KB smem) so the L1 carveout stays ~220KB for the prefetch window
// (R10's 127KB partials array was strangling it).
// Thread t owns cell t, 36 coefs in registers; warps staggered across the
// CTA's b-list; no barriers in the loop.

#define GG    961
#define CC    36
#define NTHR  992
#define NWARP 31
#define MAXK  28
#define D_L1  2          // L1 prefetch distance (iterations ahead of consume)
#define D_L2  8          // L2 prefetch distance

__global__ __launch_bounds__(NTHR, 1)
void sq2d_kernel(const float* __restrict__ param,
                 const float* __restrict__ coef,
                 float* __restrict__ out,
                 int nB, int stride)
{
    __shared__ float part[MAXK * 32];   // [k][warp]

    const int tid  = threadIdx.x;
    const int lane = tid & 31;
    const int warp = tid >> 5;
    const bool active = (tid < GG);
    const int cell = active ? tid : (GG - 1);   // pad threads dup cell 960

    // 36 coefficients in registers (0 for pad threads).
    float cf[CC];
#pragma unroll
    for (int c = 0; c < CC; c++)
        cf[c] = active ? coef[cell * CC + c] : 0.0f;

    const int bid = blockIdx.x;
    const int K = (nB - bid + stride - 1) / stride;   // ~27 b's per CTA

    const char* base0 = (const char*)param + (size_t)cell * 32
                      + (size_t)bid * (size_t)GG * 32;
    const size_t bstep = (size_t)GG * 32 * (size_t)stride;

    // Staggered start within this CTA's b-list.
    int k = (warp * K) / NWARP;        // index of the load currently in flight
    if (k >= K) k = K - 1;

    // 9 lanes/warp cover the warp's (possibly line-straddling) 1KB slab.
    const bool pf_lane = ((lane & 3) == 0) || (lane == 31);

    // Prologue: issue the first consumer load (k) and warm the prefetches.
    float n0, n1, n2, n3, n4, n5, n6, n7;
    {
        const char* p = base0 + (size_t)k * bstep;
        asm volatile("ld.global.nc.v4.f32 {%0,%1,%2,%3}, [%4];"
                     : "=f"(n0), "=f"(n1), "=f"(n2), "=f"(n3) : "l"(p));
        asm volatile("ld.global.nc.v4.f32 {%0,%1,%2,%3}, [%4+16];"
                     : "=f"(n4), "=f"(n5), "=f"(n6), "=f"(n7) : "l"(p));
        if (pf_lane) {
            int k1 = k + 1; if (k1 >= K) k1 -= K;
            const char* q1 = base0 + (size_t)k1 * bstep;
            asm volatile("prefetch.global.L1 [%0];" :: "l"(q1));
#pragma unroll
            for (int d = 2; d < D_L2; d++) {
                int k2 = k + d; while (k2 >= K) k2 -= K;
                const char* q2 = base0 + (size_t)k2 * bstep;
                asm volatile("prefetch.global.L2 [%0];" :: "l"(q2));
            }
        }
    }

#pragma unroll 1
    for (int j = 0; j < K; j++) {
        // Retire in-flight values into pv with movs (WAR dies in 4 cyc).
        float pv0, pv1, pv2, pv3, pv4, pv5, pv6, pv7;
        asm volatile("mov.f32 %0, %1;" : "=f"(pv0) : "f"(n0));
        asm volatile("mov.f32 %0, %1;" : "=f"(pv1) : "f"(n1));
        asm volatile("mov.f32 %0, %1;" : "=f"(pv2) : "f"(n2));
        asm volatile("mov.f32 %0, %1;" : "=f"(pv3) : "f"(n3));
        asm volatile("mov.f32 %0, %1;" : "=f"(pv4) : "f"(n4));
        asm volatile("mov.f32 %0, %1;" : "=f"(pv5) : "f"(n5));
        asm volatile("mov.f32 %0, %1;" : "=f"(pv6) : "f"(n6));
        asm volatile("mov.f32 %0, %1;" : "=f"(pv7) : "f"(n7));

        const int kc = k;                 // b-slot now in pv

        // Advance; issue next consumer load + staged prefetches BEFORE FMAs.
        k = k + 1; if (k == K) k = 0;
        {
            const char* p = base0 + (size_t)k * bstep;
            asm volatile("ld.global.nc.v4.f32 {%0,%1,%2,%3}, [%4];"
                         : "=f"(n0), "=f"(n1), "=f"(n2), "=f"(n3) : "l"(p));
            asm volatile("ld.global.nc.v4.f32 {%0,%1,%2,%3}, [%4+16];"
                         : "=f"(n4), "=f"(n5), "=f"(n6), "=f"(n7) : "l"(p));
        }
        if (pf_lane) {
            int k1 = k + (D_L1 - 1); if (k1 >= K) k1 -= K;
            const char* q1 = base0 + (size_t)k1 * bstep;
            asm volatile("prefetch.global.L1 [%0];" :: "l"(q1));
            int k2 = k + (D_L2 - 1); while (k2 >= K) k2 -= K;
            const char* q2 = base0 + (size_t)k2 * bstep;
            asm volatile("prefetch.global.L2 [%0];" :: "l"(q2));
        }

        float pv[8] = { pv0, pv1, pv2, pv3, pv4, pv5, pv6, pv7 };

        // acc = sum_{i<=j} cf[c(i,j)] * p_i * p_j : 44 FMA.
        float acc = 0.0f;
        int c = 0;
#pragma unroll
        for (int i = 0; i < 8; i++) {
            float q = 0.0f;
#pragma unroll
            for (int jj = i; jj < 8; jj++)
                q = fmaf(cf[c++], pv[jj], q);
            acc = fmaf(pv[i], q, acc);
        }

        // Warp reduce; one STS per warp per b. No block coupling in the loop.
#pragma unroll
        for (int o = 16; o > 0; o >>= 1)
            acc += __shfl_xor_sync(0xffffffffu, acc, o);
        if (lane == 0)
            part[kc * 32 + warp] = acc;
    }

    __syncthreads();   // the only block barrier

    // Warp w finalizes b = bid + w*stride.
    if (warp < K) {
        float v = (lane < NWARP) ? part[warp * 32 + lane] : 0.0f;
#pragma unroll
        for (int o = 16; o > 0; o >>= 1)
            v += __shfl_xor_sync(0xffffffffu, v, o);
        if (lane == 0)
            out[bid + warp * stride] = v;
    }
}

extern "C" void kernel_launch(void* const* d_in, const int* in_sizes, int n_in,
                              void* d_out, int out_size)
{
    const float* param = (const float*)d_in[0];   // [B, 31, 31, 8] f32
    const float* coef  = (const float*)d_in[1];   // [31, 31, 36]   f32
    float* out = (float*)d_out;                    // [B] f32

    const int nB = in_sizes[0] / (GG * 8);

    int dev = 0, sms = 0;
    cudaGetDevice(&dev);
    cudaDeviceGetAttribute(&sms, cudaDevAttrMultiProcessorCount, dev);
    if (sms <= 0) sms = 148;

    int grid = sms;
    const int min_grid = (nB + MAXK - 1) / MAXK;   // keep K <= MAXK
    if (grid < min_grid) grid = min_grid;
    if (grid > nB) grid = nB;

    sq2d_kernel<<<grid, NTHR>>>(param, coef, out, nB, grid);
}